// round 1
// baseline (speedup 1.0000x reference)
#include <cuda_runtime.h>
#include <cuda_bf16.h>
#include <stdint.h>

#define NN 100000
#define NE 1600000
#define NG 64

// ---------------- static device scratch (allocation-free rule) ----------------
static __device__ float g_deg[NN];          // degree -> deg_inv_sqrt (in place)
static __device__ float g_norm[NE];         // per-edge normalized weight
static __device__ float g_TA[(size_t)NN * 128];
static __device__ float g_TB[(size_t)NN * 128];
static __device__ float g_H1[(size_t)NN * 64];
static __device__ float g_H2[(size_t)NN * 64];
static __device__ float g_H3[(size_t)NN * 128];
static __device__ float g_sums[NG * 128];
static __device__ float g_cnt[NG];
static __device__ int   g_is64;

// ---------------- helpers ----------------
__device__ __forceinline__ long ldidx(const void* p, long i) {
    if (g_is64) return (long)((const long long*)p)[i];
    return (long)((const int*)p)[i];
}

__device__ __forceinline__ void redAdd4(float* p, float x, float y, float z, float w) {
#if __CUDA_ARCH__ >= 900
    asm volatile("red.global.add.v4.f32 [%0], {%1, %2, %3, %4};"
                 :: "l"(p), "f"(x), "f"(y), "f"(z), "f"(w) : "memory");
#else
    atomicAdd(p + 0, x); atomicAdd(p + 1, y); atomicAdd(p + 2, z); atomicAdd(p + 3, w);
#endif
}

// ---------------- index dtype detection ----------------
// int64 little-endian: odd 32-bit words (high halves) are all zero for indices < 2^31.
// int32 random indices in [0,1e5): P(128 consecutive odd words all zero) ~ 0.
__global__ void detect64_kernel(const unsigned int* __restrict__ w) {
    int is64 = 1;
    for (int i = 0; i < 128; i++) {
        if (w[2 * i + 1] != 0u) { is64 = 0; break; }
    }
    g_is64 = is64;
}

// ---------------- degree + norm ----------------
__global__ void deg_accum_kernel(const void* __restrict__ ei, const float* __restrict__ ea, long E) {
    long e = (long)blockIdx.x * blockDim.x + threadIdx.x;
    if (e >= E) return;
    long src = ldidx(ei, e);
    atomicAdd(&g_deg[src], ea[e]);
}

__global__ void finalize_deg_kernel(long N) {
    long n = (long)blockIdx.x * blockDim.x + threadIdx.x;
    if (n >= N) return;
    float d = g_deg[n];
    g_deg[n] = (d > 0.0f) ? rsqrtf(d) : 0.0f;
}

__global__ void norm_kernel(const void* __restrict__ ei, const float* __restrict__ ea, long E) {
    long e = (long)blockIdx.x * blockDim.x + threadIdx.x;
    if (e >= E) return;
    long src = ldidx(ei, e);
    long dst = ldidx(ei, E + e);
    g_norm[e] = -g_deg[src] * ea[e] * g_deg[dst];
}

// ---------------- sparse propagation: out[dst] += norm * x[src] ----------------
template <int F>
__global__ void prop_kernel(const float* __restrict__ x, float* __restrict__ out,
                            const float* __restrict__ nw, const void* __restrict__ ei, long E) {
    constexpr int TPE = F / 4;  // threads per edge, each handles a float4
    long t = (long)blockIdx.x * blockDim.x + threadIdx.x;
    long e = t / TPE;
    int  c = (int)(t - e * TPE);
    if (e >= E) return;
    float w = nw[e];
    long src = ldidx(ei, e);
    long dst = ldidx(ei, E + e);
    const float4 v = *reinterpret_cast<const float4*>(x + src * (long)F + c * 4);
    redAdd4(out + dst * (long)F + c * 4, v.x * w, v.y * w, v.z * w, v.w * w);
}

// ---------------- fused Chebyshev combine + bias + ReLU ----------------
// out = relu( T0@(W0-W2) + T1@W1 + T2raw@(2*W2) + b ), weight transform in smem.
template <int Fin, int Fout, bool RELU>
__global__ void combine_kernel(const float* __restrict__ T0, const float* __restrict__ T1,
                               const float* __restrict__ T2, const float* __restrict__ W,
                               const float* __restrict__ b, float* __restrict__ out, long N) {
    constexpr int TM = 256 / Fout;
    constexpr int S = Fin * Fout;
    extern __shared__ float sm[];
    float* sW = sm;            // 3*S floats
    float* sT = sm + 3 * S;    // 3*TM*Fin floats
    const int tid = threadIdx.x;

    for (int i = tid; i < S; i += 256) {
        float w0 = W[i], w1 = W[S + i], w2 = W[2 * S + i];
        sW[i] = w0 - w2;
        sW[S + i] = w1;
        sW[2 * S + i] = 2.0f * w2;
    }

    const long base = (long)blockIdx.x * TM;
    const float* Ts[3] = {T0, T1, T2};
    for (int i = tid; i < 3 * TM * Fin; i += 256) {
        int k = i / (TM * Fin);
        int r = i - k * (TM * Fin);
        int ln = r / Fin;
        int f = r - ln * Fin;
        long node = base + ln;
        sT[i] = (node < N) ? Ts[k][node * (long)Fin + f] : 0.0f;
    }
    __syncthreads();

    const int fo = tid % Fout;
    const int ln = tid / Fout;
    const long node = base + ln;
    if (node >= N) return;

    float acc = b[fo];
#pragma unroll
    for (int k = 0; k < 3; k++) {
        const float* tr = &sT[(k * TM + ln) * Fin];
        const float* wc = &sW[k * S + fo];
#pragma unroll 8
        for (int f = 0; f < Fin; f++)
            acc += tr[f] * wc[f * Fout];
    }
    if (RELU) acc = fmaxf(acc, 0.0f);
    out[node * (long)Fout + fo] = acc;
}

// ---------------- pooling ----------------
__global__ void pool_kernel(const float* __restrict__ h, const void* __restrict__ batch, long N) {
    long t = (long)blockIdx.x * blockDim.x + threadIdx.x;
    long node = t >> 5;       // 32 threads per node (128 feats as float4)
    int c = (int)(t & 31);
    if (node >= N) return;
    int g = (int)ldidx(batch, node);
    const float4 v = *reinterpret_cast<const float4*>(h + node * 128 + c * 4);
    redAdd4(&g_sums[g * 128 + c * 4], v.x, v.y, v.z, v.w);
}

__global__ void count_kernel(const void* __restrict__ batch, long N) {
    long n = (long)blockIdx.x * blockDim.x + threadIdx.x;
    if (n >= N) return;
    atomicAdd(&g_cnt[(int)ldidx(batch, n)], 1.0f);
}

// ---------------- final linear: out[g] = (sums[g]/cnt[g]) @ lin_W + lin_b ----------------
__global__ void final_kernel(const float* __restrict__ lw, const float* __restrict__ lb,
                             float* __restrict__ out) {
    __shared__ float sp[128];
    int g = blockIdx.x;
    float inv = 1.0f / fmaxf(g_cnt[g], 1.0f);
    for (int i = threadIdx.x; i < 128; i += 32)
        sp[i] = g_sums[g * 128 + i] * inv;
    __syncthreads();
    if (threadIdx.x < 10) {
        float acc = lb[threadIdx.x];
#pragma unroll 8
        for (int f = 0; f < 128; f++)
            acc += sp[f] * lw[f * 10 + threadIdx.x];
        out[g * 10 + threadIdx.x] = acc;
    }
}

static inline int cdivl(long a, long b) { return (int)((a + b - 1) / b); }

extern "C" void kernel_launch(void* const* d_in, const int* in_sizes, int n_in,
                              void* d_out, int out_size) {
    const float* x    = (const float*)d_in[0];
    const void*  ei   = d_in[1];
    const float* ea   = (const float*)d_in[2];
    const void*  bat  = d_in[3];
    const float* W1   = (const float*)d_in[4];
    const float* b1   = (const float*)d_in[5];
    const float* W2   = (const float*)d_in[6];
    const float* b2   = (const float*)d_in[7];
    const float* W3   = (const float*)d_in[8];
    const float* b3   = (const float*)d_in[9];
    const float* linW = (const float*)d_in[10];
    const float* linB = (const float*)d_in[11];
    float* out = (float*)d_out;

    const long E = in_sizes[2];   // 1.6M
    const long N = in_sizes[3];   // 100k

    float *pDeg, *pNorm, *pTA, *pTB, *pH1, *pH2, *pH3, *pSums, *pCnt;
    cudaGetSymbolAddress((void**)&pDeg, g_deg);
    cudaGetSymbolAddress((void**)&pNorm, g_norm);
    cudaGetSymbolAddress((void**)&pTA, g_TA);
    cudaGetSymbolAddress((void**)&pTB, g_TB);
    cudaGetSymbolAddress((void**)&pH1, g_H1);
    cudaGetSymbolAddress((void**)&pH2, g_H2);
    cudaGetSymbolAddress((void**)&pH3, g_H3);
    cudaGetSymbolAddress((void**)&pSums, g_sums);
    cudaGetSymbolAddress((void**)&pCnt, g_cnt);

    const size_t SM1 = (3 * 128 * 64 + 3 * 4 * 128) * sizeof(float);  // 104448
    const size_t SM2 = (3 * 64 * 64 + 3 * 4 * 64) * sizeof(float);    // 52224
    const size_t SM3 = (3 * 64 * 128 + 3 * 2 * 64) * sizeof(float);   // 99840
    cudaFuncSetAttribute(combine_kernel<128, 64, true>, cudaFuncAttributeMaxDynamicSharedMemorySize, (int)SM1);
    cudaFuncSetAttribute(combine_kernel<64, 64, true>, cudaFuncAttributeMaxDynamicSharedMemorySize, (int)SM2);
    cudaFuncSetAttribute(combine_kernel<64, 128, true>, cudaFuncAttributeMaxDynamicSharedMemorySize, (int)SM3);

    // index dtype detection (device-side, deterministic)
    detect64_kernel<<<1, 1>>>((const unsigned int*)ei);

    // degree + normalized edge weights
    cudaMemsetAsync(pDeg, 0, NN * sizeof(float));
    deg_accum_kernel<<<cdivl(E, 256), 256>>>(ei, ea, E);
    finalize_deg_kernel<<<cdivl(N, 256), 256>>>(N);
    norm_kernel<<<cdivl(E, 256), 256>>>(ei, ea, E);

    // ---- Layer 1 (128 -> 64) ----
    cudaMemsetAsync(pTA, 0, (size_t)NN * 128 * sizeof(float));
    prop_kernel<128><<<cdivl(E * 32, 256), 256>>>(x, pTA, pNorm, ei, E);
    cudaMemsetAsync(pTB, 0, (size_t)NN * 128 * sizeof(float));
    prop_kernel<128><<<cdivl(E * 32, 256), 256>>>(pTA, pTB, pNorm, ei, E);
    combine_kernel<128, 64, true><<<cdivl(N, 4), 256, SM1>>>(x, pTA, pTB, W1, b1, pH1, N);

    // ---- Layer 2 (64 -> 64) ----
    cudaMemsetAsync(pTA, 0, (size_t)NN * 64 * sizeof(float));
    prop_kernel<64><<<cdivl(E * 16, 256), 256>>>(pH1, pTA, pNorm, ei, E);
    cudaMemsetAsync(pTB, 0, (size_t)NN * 64 * sizeof(float));
    prop_kernel<64><<<cdivl(E * 16, 256), 256>>>(pTA, pTB, pNorm, ei, E);
    combine_kernel<64, 64, true><<<cdivl(N, 4), 256, SM2>>>(pH1, pTA, pTB, W2, b2, pH2, N);

    // ---- Layer 3 (64 -> 128) ----
    cudaMemsetAsync(pTA, 0, (size_t)NN * 64 * sizeof(float));
    prop_kernel<64><<<cdivl(E * 16, 256), 256>>>(pH2, pTA, pNorm, ei, E);
    cudaMemsetAsync(pTB, 0, (size_t)NN * 64 * sizeof(float));
    prop_kernel<64><<<cdivl(E * 16, 256), 256>>>(pTA, pTB, pNorm, ei, E);
    combine_kernel<64, 128, true><<<cdivl(N, 2), 256, SM3>>>(pH2, pTA, pTB, W3, b3, pH3, N);

    // ---- global mean pool + linear head ----
    cudaMemsetAsync(pSums, 0, NG * 128 * sizeof(float));
    cudaMemsetAsync(pCnt, 0, NG * sizeof(float));
    pool_kernel<<<cdivl(N * 32, 256), 256>>>(pH3, bat, N);
    count_kernel<<<cdivl(N, 256), 256>>>(bat, N);
    final_kernel<<<NG, 32>>>(linW, linB, out);
}

// round 2
// speedup vs baseline: 1.2174x; 1.2174x over previous
#include <cuda_runtime.h>
#include <cuda_bf16.h>
#include <stdint.h>

#define NN 100000
#define NE 1600000
#define NG 64
#define SCAN_BLK 1024

// ---------------- static device scratch (allocation-free rule) ----------------
static __device__ float g_deg[NN];             // degree -> deg_inv_sqrt (in place)
static __device__ int   g_cnti[NN];            // in-degree histogram (by dst)
static __device__ int   g_rowptr[NN + 1];      // CSR row pointers (dst-major)
static __device__ int   g_offs[NN];            // running offsets for scatter
static __device__ int   g_bsum[128];           // scan block sums
static __device__ int   g_csr_src[NE];
static __device__ float g_csr_w[NE];
static __device__ float g_TA[(size_t)NN * 128];
static __device__ float g_TB[(size_t)NN * 128];
static __device__ float g_H1[(size_t)NN * 64];
static __device__ float g_H2[(size_t)NN * 64];
static __device__ float g_H3[(size_t)NN * 128];
static __device__ float g_sums[NG * 128];
static __device__ float g_cnt[NG];
static __device__ int   g_is64;

// ---------------- helpers ----------------
__device__ __forceinline__ long ldidx(const void* p, long i) {
    if (g_is64) return (long)((const long long*)p)[i];
    return (long)((const int*)p)[i];
}

__device__ __forceinline__ void redAdd4(float* p, float x, float y, float z, float w) {
    asm volatile("red.global.add.v4.f32 [%0], {%1, %2, %3, %4};"
                 :: "l"(p), "f"(x), "f"(y), "f"(z), "f"(w) : "memory");
}

// ---------------- index dtype detection ----------------
__global__ void detect64_kernel(const unsigned int* __restrict__ w) {
    int is64 = 1;
    for (int i = 0; i < 128; i++) {
        if (w[2 * i + 1] != 0u) { is64 = 0; break; }
    }
    g_is64 = is64;
}

// ---------------- degree (by src) + in-degree histogram (by dst), one edge pass ----------------
__global__ void deg_hist_kernel(const void* __restrict__ ei, const float* __restrict__ ea, long E) {
    long e = (long)blockIdx.x * blockDim.x + threadIdx.x;
    if (e >= E) return;
    long src = ldidx(ei, e);
    long dst = ldidx(ei, E + e);
    atomicAdd(&g_deg[src], ea[e]);
    atomicAdd(&g_cnti[dst], 1);
}

__global__ void finalize_deg_kernel(long N) {
    long n = (long)blockIdx.x * blockDim.x + threadIdx.x;
    if (n >= N) return;
    float d = g_deg[n];
    g_deg[n] = (d > 0.0f) ? rsqrtf(d) : 0.0f;
}

// ---------------- exclusive scan over g_cnti -> g_rowptr (3 kernels) ----------------
__global__ void scan_local_kernel(int n) {
    __shared__ int sm[SCAN_BLK];
    int gid = blockIdx.x * SCAN_BLK + threadIdx.x;
    int v = (gid < n) ? g_cnti[gid] : 0;
    sm[threadIdx.x] = v;
    __syncthreads();
    for (int off = 1; off < SCAN_BLK; off <<= 1) {
        int t = (threadIdx.x >= off) ? sm[threadIdx.x - off] : 0;
        __syncthreads();
        sm[threadIdx.x] += t;
        __syncthreads();
    }
    if (gid < n) g_rowptr[gid] = sm[threadIdx.x] - v;   // exclusive
    if (threadIdx.x == SCAN_BLK - 1) g_bsum[blockIdx.x] = sm[SCAN_BLK - 1];
}

__global__ void scan_bsum_kernel(int nb) {
    __shared__ int sm[128];
    int v = (threadIdx.x < nb) ? g_bsum[threadIdx.x] : 0;
    sm[threadIdx.x] = v;
    __syncthreads();
    for (int off = 1; off < 128; off <<= 1) {
        int t = (threadIdx.x >= off) ? sm[threadIdx.x - off] : 0;
        __syncthreads();
        sm[threadIdx.x] += t;
        __syncthreads();
    }
    if (threadIdx.x < nb) g_bsum[threadIdx.x] = sm[threadIdx.x] - v;  // exclusive
}

__global__ void scan_add_kernel(int n, int E) {
    int gid = blockIdx.x * SCAN_BLK + threadIdx.x;
    if (gid < n) {
        int v = g_rowptr[gid] + g_bsum[blockIdx.x];
        g_rowptr[gid] = v;
        g_offs[gid] = v;
    }
    if (gid == 0) g_rowptr[n] = E;
}

// ---------------- bucket scatter: edges into dst-major CSR, norm folded in ----------------
__global__ void scatter_kernel(const void* __restrict__ ei, const float* __restrict__ ea, long E) {
    long e = (long)blockIdx.x * blockDim.x + threadIdx.x;
    if (e >= E) return;
    int src = (int)ldidx(ei, e);
    int dst = (int)ldidx(ei, E + e);
    int pos = atomicAdd(&g_offs[dst], 1);
    g_csr_src[pos] = src;
    g_csr_w[pos] = -g_deg[src] * ea[e] * g_deg[dst];
}

// ---------------- dst-major pull propagation: out[n] = sum_e w_e * x[src_e] ----------------
template <int F>
__global__ void prop_csr_kernel(const float* __restrict__ x, float* __restrict__ out, long N) {
    constexpr int TPN = F / 4;  // threads per node, each owns one float4 column
    long t = (long)blockIdx.x * blockDim.x + threadIdx.x;
    long n = t / TPN;
    int c = (int)(t - n * TPN);
    if (n >= N) return;
    int p = g_rowptr[n], end = g_rowptr[n + 1];
    float4 a0 = {0.f, 0.f, 0.f, 0.f}, a1 = {0.f, 0.f, 0.f, 0.f};
    for (; p + 2 <= end; p += 2) {
        int s0 = g_csr_src[p], s1 = g_csr_src[p + 1];
        float w0 = g_csr_w[p], w1 = g_csr_w[p + 1];
        float4 v0 = __ldg(reinterpret_cast<const float4*>(x + (long)s0 * F) + c);
        float4 v1 = __ldg(reinterpret_cast<const float4*>(x + (long)s1 * F) + c);
        a0.x += w0 * v0.x; a0.y += w0 * v0.y; a0.z += w0 * v0.z; a0.w += w0 * v0.w;
        a1.x += w1 * v1.x; a1.y += w1 * v1.y; a1.z += w1 * v1.z; a1.w += w1 * v1.w;
    }
    if (p < end) {
        int s0 = g_csr_src[p];
        float w0 = g_csr_w[p];
        float4 v0 = __ldg(reinterpret_cast<const float4*>(x + (long)s0 * F) + c);
        a0.x += w0 * v0.x; a0.y += w0 * v0.y; a0.z += w0 * v0.z; a0.w += w0 * v0.w;
    }
    a0.x += a1.x; a0.y += a1.y; a0.z += a1.z; a0.w += a1.w;
    reinterpret_cast<float4*>(out + n * (long)F)[c] = a0;
}

// ---------------- fused Chebyshev combine + bias + ReLU ----------------
// out = relu( T0@(W0-W2) + T1@W1 + T2raw@(2*W2) + b ), weight transform in smem.
template <int Fin, int Fout, bool RELU>
__global__ void combine_kernel(const float* __restrict__ T0, const float* __restrict__ T1,
                               const float* __restrict__ T2, const float* __restrict__ W,
                               const float* __restrict__ b, float* __restrict__ out, long N) {
    constexpr int TM = 256 / Fout;
    constexpr int S = Fin * Fout;
    extern __shared__ float sm[];
    float* sW = sm;            // 3*S floats
    float* sT = sm + 3 * S;    // 3*TM*Fin floats
    const int tid = threadIdx.x;

    for (int i = tid; i < S; i += 256) {
        float w0 = W[i], w1 = W[S + i], w2 = W[2 * S + i];
        sW[i] = w0 - w2;
        sW[S + i] = w1;
        sW[2 * S + i] = 2.0f * w2;
    }

    const long base = (long)blockIdx.x * TM;
    const float* Ts[3] = {T0, T1, T2};
    for (int i = tid; i < 3 * TM * Fin; i += 256) {
        int k = i / (TM * Fin);
        int r = i - k * (TM * Fin);
        int ln = r / Fin;
        int f = r - ln * Fin;
        long node = base + ln;
        sT[i] = (node < N) ? Ts[k][node * (long)Fin + f] : 0.0f;
    }
    __syncthreads();

    const int fo = tid % Fout;
    const int ln = tid / Fout;
    const long node = base + ln;
    if (node >= N) return;

    float acc = b[fo];
#pragma unroll
    for (int k = 0; k < 3; k++) {
        const float* tr = &sT[(k * TM + ln) * Fin];
        const float* wc = &sW[k * S + fo];
#pragma unroll 8
        for (int f = 0; f < Fin; f++)
            acc += tr[f] * wc[f * Fout];
    }
    if (RELU) acc = fmaxf(acc, 0.0f);
    out[node * (long)Fout + fo] = acc;
}

// ---------------- pooling ----------------
__global__ void pool_kernel(const float* __restrict__ h, const void* __restrict__ batch, long N) {
    long t = (long)blockIdx.x * blockDim.x + threadIdx.x;
    long node = t >> 5;       // 32 threads per node (128 feats as float4)
    int c = (int)(t & 31);
    if (node >= N) return;
    int g = (int)ldidx(batch, node);
    const float4 v = *reinterpret_cast<const float4*>(h + node * 128 + c * 4);
    redAdd4(&g_sums[g * 128 + c * 4], v.x, v.y, v.z, v.w);
}

__global__ void count_kernel(const void* __restrict__ batch, long N) {
    long n = (long)blockIdx.x * blockDim.x + threadIdx.x;
    if (n >= N) return;
    atomicAdd(&g_cnt[(int)ldidx(batch, n)], 1.0f);
}

// ---------------- final linear: out[g] = (sums[g]/cnt[g]) @ lin_W + lin_b ----------------
__global__ void final_kernel(const float* __restrict__ lw, const float* __restrict__ lb,
                             float* __restrict__ out) {
    __shared__ float sp[128];
    int g = blockIdx.x;
    float inv = 1.0f / fmaxf(g_cnt[g], 1.0f);
    for (int i = threadIdx.x; i < 128; i += 32)
        sp[i] = g_sums[g * 128 + i] * inv;
    __syncthreads();
    if (threadIdx.x < 10) {
        float acc = lb[threadIdx.x];
#pragma unroll 8
        for (int f = 0; f < 128; f++)
            acc += sp[f] * lw[f * 10 + threadIdx.x];
        out[g * 10 + threadIdx.x] = acc;
    }
}

static inline int cdivl(long a, long b) { return (int)((a + b - 1) / b); }

extern "C" void kernel_launch(void* const* d_in, const int* in_sizes, int n_in,
                              void* d_out, int out_size) {
    const float* x    = (const float*)d_in[0];
    const void*  ei   = d_in[1];
    const float* ea   = (const float*)d_in[2];
    const void*  bat  = d_in[3];
    const float* W1   = (const float*)d_in[4];
    const float* b1   = (const float*)d_in[5];
    const float* W2   = (const float*)d_in[6];
    const float* b2   = (const float*)d_in[7];
    const float* W3   = (const float*)d_in[8];
    const float* b3   = (const float*)d_in[9];
    const float* linW = (const float*)d_in[10];
    const float* linB = (const float*)d_in[11];
    float* out = (float*)d_out;

    const long E = in_sizes[2];   // 1.6M
    const long N = in_sizes[3];   // 100k

    float *pDeg, *pTA, *pTB, *pH1, *pH2, *pH3, *pSums, *pCnt;
    int *pCnti;
    cudaGetSymbolAddress((void**)&pDeg, g_deg);
    cudaGetSymbolAddress((void**)&pCnti, g_cnti);
    cudaGetSymbolAddress((void**)&pTA, g_TA);
    cudaGetSymbolAddress((void**)&pTB, g_TB);
    cudaGetSymbolAddress((void**)&pH1, g_H1);
    cudaGetSymbolAddress((void**)&pH2, g_H2);
    cudaGetSymbolAddress((void**)&pH3, g_H3);
    cudaGetSymbolAddress((void**)&pSums, g_sums);
    cudaGetSymbolAddress((void**)&pCnt, g_cnt);

    const size_t SM1 = (3 * 128 * 64 + 3 * 4 * 128) * sizeof(float);  // 104448
    const size_t SM2 = (3 * 64 * 64 + 3 * 4 * 64) * sizeof(float);    // 52224
    const size_t SM3 = (3 * 64 * 128 + 3 * 2 * 64) * sizeof(float);   // 99840
    cudaFuncSetAttribute(combine_kernel<128, 64, true>, cudaFuncAttributeMaxDynamicSharedMemorySize, (int)SM1);
    cudaFuncSetAttribute(combine_kernel<64, 64, true>, cudaFuncAttributeMaxDynamicSharedMemorySize, (int)SM2);
    cudaFuncSetAttribute(combine_kernel<64, 128, true>, cudaFuncAttributeMaxDynamicSharedMemorySize, (int)SM3);

    // index dtype detection (device-side, deterministic)
    detect64_kernel<<<1, 1>>>((const unsigned int*)ei);

    // ---- degree + CSR build (dst-major) ----
    cudaMemsetAsync(pDeg, 0, NN * sizeof(float));
    cudaMemsetAsync(pCnti, 0, NN * sizeof(int));
    deg_hist_kernel<<<cdivl(E, 256), 256>>>(ei, ea, E);
    finalize_deg_kernel<<<cdivl(N, 256), 256>>>(N);
    const int nScanBlocks = cdivl(N, SCAN_BLK);   // 98
    scan_local_kernel<<<nScanBlocks, SCAN_BLK>>>((int)N);
    scan_bsum_kernel<<<1, 128>>>(nScanBlocks);
    scan_add_kernel<<<nScanBlocks, SCAN_BLK>>>((int)N, (int)E);
    scatter_kernel<<<cdivl(E, 256), 256>>>(ei, ea, E);

    // ---- Layer 1 (128 -> 64) ----
    prop_csr_kernel<128><<<cdivl(N * 32, 256), 256>>>(x, pTA, N);
    prop_csr_kernel<128><<<cdivl(N * 32, 256), 256>>>(pTA, pTB, N);
    combine_kernel<128, 64, true><<<cdivl(N, 4), 256, SM1>>>(x, pTA, pTB, W1, b1, pH1, N);

    // ---- Layer 2 (64 -> 64) ----
    prop_csr_kernel<64><<<cdivl(N * 16, 256), 256>>>(pH1, pTA, N);
    prop_csr_kernel<64><<<cdivl(N * 16, 256), 256>>>(pTA, pTB, N);
    combine_kernel<64, 64, true><<<cdivl(N, 4), 256, SM2>>>(pH1, pTA, pTB, W2, b2, pH2, N);

    // ---- Layer 3 (64 -> 128) ----
    prop_csr_kernel<64><<<cdivl(N * 16, 256), 256>>>(pH2, pTA, N);
    prop_csr_kernel<64><<<cdivl(N * 16, 256), 256>>>(pTA, pTB, N);
    combine_kernel<64, 128, true><<<cdivl(N, 2), 256, SM3>>>(pH2, pTA, pTB, W3, b3, pH3, N);

    // ---- global mean pool + linear head ----
    cudaMemsetAsync(pSums, 0, NG * 128 * sizeof(float));
    cudaMemsetAsync(pCnt, 0, NG * sizeof(float));
    pool_kernel<<<cdivl(N * 32, 256), 256>>>(pH3, bat, N);
    count_kernel<<<cdivl(N, 256), 256>>>(bat, N);
    final_kernel<<<NG, 32>>>(linW, linB, out);
}

// round 3
// speedup vs baseline: 2.7759x; 2.2802x over previous
#include <cuda_runtime.h>
#include <cuda_bf16.h>
#include <stdint.h>

#define NN 100000
#define NE 1600000
#define NG 64

// ---------------- static device scratch (allocation-free rule) ----------------
static __device__ float g_deg[NN];
static __device__ int   g_cnti[NN];
static __device__ int   g_rowptr[NN + 1];
static __device__ int   g_offs[NN];
static __device__ int   g_csr_src[NE];
static __device__ float g_csr_w[NE];
static __device__ float g_TA[(size_t)NN * 128];
static __device__ float g_TB[(size_t)NN * 128];
static __device__ float g_H1[(size_t)NN * 64];
static __device__ float g_H2[(size_t)NN * 64];
static __device__ float g_H3[(size_t)NN * 128];
static __device__ float g_sums[NG * 128];
static __device__ float g_cnt[NG];
static __device__ int   g_is64;

// ---------------- helpers ----------------
__device__ __forceinline__ long ldidx(const void* p, long i) {
    if (g_is64) return (long)((const long long*)p)[i];
    return (long)((const int*)p)[i];
}

__device__ __forceinline__ float rinv(float d) { return (d > 0.0f) ? rsqrtf(d) : 0.0f; }

__device__ __forceinline__ void redAdd4(float* p, float x, float y, float z, float w) {
    asm volatile("red.global.add.v4.f32 [%0], {%1, %2, %3, %4};"
                 :: "l"(p), "f"(x), "f"(y), "f"(z), "f"(w) : "memory");
}

// ---------------- init: zero deg/cnti + index dtype detection ----------------
__global__ void init_kernel(const unsigned int* __restrict__ w, int N) {
    int gid = blockIdx.x * blockDim.x + threadIdx.x;
    if (gid < N) { g_deg[gid] = 0.0f; g_cnti[gid] = 0; }
    if (gid == 0) {
        int is64 = 1;
        for (int i = 0; i < 128; i++) {
            if (w[2 * i + 1] != 0u) { is64 = 0; break; }
        }
        g_is64 = is64;
    }
}

// ---------------- degree (by src) + in-degree histogram (by dst) ----------------
__global__ void deg_hist_kernel(const void* __restrict__ ei, const float* __restrict__ ea, long E) {
    long e = (long)blockIdx.x * blockDim.x + threadIdx.x;
    if (e >= E) return;
    long src = ldidx(ei, e);
    long dst = ldidx(ei, E + e);
    atomicAdd(&g_deg[src], ea[e]);
    atomicAdd(&g_cnti[dst], 1);
}

// ---------------- single-block exclusive scan (shuffle-based) ----------------
__global__ void scan_kernel(int n, int E) {
    __shared__ int wsum[32];
    __shared__ int carry_s;
    const int lane = threadIdx.x & 31, wid = threadIdx.x >> 5;
    if (threadIdx.x == 0) carry_s = 0;
    __syncthreads();
    for (int base = 0; base < n; base += 1024) {
        int gid = base + threadIdx.x;
        int v = (gid < n) ? g_cnti[gid] : 0;
        int inc = v;
#pragma unroll
        for (int off = 1; off < 32; off <<= 1) {
            int t = __shfl_up_sync(0xFFFFFFFFu, inc, off);
            if (lane >= off) inc += t;
        }
        if (lane == 31) wsum[wid] = inc;
        __syncthreads();
        if (wid == 0) {
            int s = wsum[lane];
            int si = s;
#pragma unroll
            for (int off = 1; off < 32; off <<= 1) {
                int t = __shfl_up_sync(0xFFFFFFFFu, si, off);
                if (lane >= off) si += t;
            }
            wsum[lane] = si - s;  // exclusive
        }
        __syncthreads();
        int excl = inc - v + wsum[wid] + carry_s;
        if (gid < n) { g_rowptr[gid] = excl; g_offs[gid] = excl; }
        __syncthreads();
        if (threadIdx.x == 1023) carry_s = excl + v;
        __syncthreads();
    }
    if (threadIdx.x == 0) g_rowptr[n] = E;
}

// ---------------- bucket scatter into dst-major CSR, norm folded in ----------------
__global__ void scatter_kernel(const void* __restrict__ ei, const float* __restrict__ ea, long E) {
    long e = (long)blockIdx.x * blockDim.x + threadIdx.x;
    if (e >= E) return;
    int src = (int)ldidx(ei, e);
    int dst = (int)ldidx(ei, E + e);
    int pos = atomicAdd(&g_offs[dst], 1);
    g_csr_src[pos] = src;
    g_csr_w[pos] = -rinv(g_deg[src]) * ea[e] * rinv(g_deg[dst]);
}

// ---------------- dst-major pull propagation, unroll-4 (MLP=4) ----------------
template <int F>
__global__ void prop_csr_kernel(const float* __restrict__ x, float* __restrict__ out, long N) {
    constexpr int TPN = F / 4;
    long t = (long)blockIdx.x * blockDim.x + threadIdx.x;
    long n = t / TPN;
    int c = (int)(t - n * TPN);
    if (n >= N) return;
    int p = g_rowptr[n], end = g_rowptr[n + 1];
    float4 a0 = {0.f, 0.f, 0.f, 0.f}, a1 = {0.f, 0.f, 0.f, 0.f};
    for (; p + 4 <= end; p += 4) {
        int s0 = g_csr_src[p], s1 = g_csr_src[p + 1], s2 = g_csr_src[p + 2], s3 = g_csr_src[p + 3];
        float w0 = g_csr_w[p], w1 = g_csr_w[p + 1], w2 = g_csr_w[p + 2], w3 = g_csr_w[p + 3];
        float4 v0 = __ldg(reinterpret_cast<const float4*>(x + (long)s0 * F) + c);
        float4 v1 = __ldg(reinterpret_cast<const float4*>(x + (long)s1 * F) + c);
        float4 v2 = __ldg(reinterpret_cast<const float4*>(x + (long)s2 * F) + c);
        float4 v3 = __ldg(reinterpret_cast<const float4*>(x + (long)s3 * F) + c);
        a0.x += w0 * v0.x; a0.y += w0 * v0.y; a0.z += w0 * v0.z; a0.w += w0 * v0.w;
        a1.x += w1 * v1.x; a1.y += w1 * v1.y; a1.z += w1 * v1.z; a1.w += w1 * v1.w;
        a0.x += w2 * v2.x; a0.y += w2 * v2.y; a0.z += w2 * v2.z; a0.w += w2 * v2.w;
        a1.x += w3 * v3.x; a1.y += w3 * v3.y; a1.z += w3 * v3.z; a1.w += w3 * v3.w;
    }
    for (; p < end; p++) {
        int s0 = g_csr_src[p];
        float w0 = g_csr_w[p];
        float4 v0 = __ldg(reinterpret_cast<const float4*>(x + (long)s0 * F) + c);
        a0.x += w0 * v0.x; a0.y += w0 * v0.y; a0.z += w0 * v0.z; a0.w += w0 * v0.w;
    }
    a0.x += a1.x; a0.y += a1.y; a0.z += a1.z; a0.w += a1.w;
    reinterpret_cast<float4*>(out + n * (long)F)[c] = a0;
}

// ---------------- register-tiled SGEMM combine + bias + ReLU ----------------
// out = relu( [T0|T1|T2raw] @ [W0-W2 ; W1 ; 2*W2] + b )
template <int Fin, int Fout, bool RELU>
__global__ void combine_gemm_kernel(const float* __restrict__ T0, const float* __restrict__ T1,
                                    const float* __restrict__ T2, const float* __restrict__ W,
                                    const float* __restrict__ bias, float* __restrict__ out, int N) {
    constexpr int BM = 64, BK = 16, BN = Fout, K3 = 3 * Fin;
    constexpr int TM = 4, TN = BN / 16;
    constexpr int S = Fin * Fout;
    __shared__ float sA[BM * BK];  // [m][kk]
    __shared__ float sB[BK * BN];  // [kk][n]
    const int tid = threadIdx.x;
    const int tx = tid % 16, ty = tid / 16;
    const int base = blockIdx.x * BM;
    const float* Ts[3] = {T0, T1, T2};

    float acc[TM][TN];
#pragma unroll
    for (int i = 0; i < TM; i++)
#pragma unroll
        for (int j = 0; j < TN; j++) acc[i][j] = 0.f;

    for (int kc = 0; kc < K3; kc += BK) {
        const int midx = kc / Fin;
        const int f0 = kc % Fin;
        const float* A = Ts[midx];
        {
            int kk = tid % 16, mb = tid / 16;
#pragma unroll
            for (int i = 0; i < 4; i++) {
                int m = mb + i * 16;
                int node = base + m;
                sA[m * BK + kk] = (node < N) ? A[(long)node * Fin + f0 + kk] : 0.f;
            }
        }
        for (int i = tid; i < BK * BN; i += 256) {
            int kk = i / BN, n = i % BN;
            int f = f0 + kk;
            float v;
            if (midx == 0)      v = W[f * Fout + n] - W[2 * S + f * Fout + n];
            else if (midx == 1) v = W[S + f * Fout + n];
            else                v = 2.f * W[2 * S + f * Fout + n];
            sB[kk * BN + n] = v;
        }
        __syncthreads();
#pragma unroll
        for (int kk = 0; kk < BK; kk++) {
            float a[TM];
#pragma unroll
            for (int i = 0; i < TM; i++) a[i] = sA[(ty * TM + i) * BK + kk];
            float b[TN];
#pragma unroll
            for (int j = 0; j < TN; j += 4) {
                float4 b4 = *reinterpret_cast<const float4*>(&sB[kk * BN + tx * TN + j]);
                b[j] = b4.x; b[j + 1] = b4.y; b[j + 2] = b4.z; b[j + 3] = b4.w;
            }
#pragma unroll
            for (int i = 0; i < TM; i++)
#pragma unroll
                for (int j = 0; j < TN; j++)
                    acc[i][j] += a[i] * b[j];
        }
        __syncthreads();
    }

#pragma unroll
    for (int i = 0; i < TM; i++) {
        int node = base + ty * TM + i;
        if (node >= N) continue;
#pragma unroll
        for (int j = 0; j < TN; j += 4) {
            int n = tx * TN + j;
            float4 v;
            v.x = acc[i][j + 0] + bias[n + 0];
            v.y = acc[i][j + 1] + bias[n + 1];
            v.z = acc[i][j + 2] + bias[n + 2];
            v.w = acc[i][j + 3] + bias[n + 3];
            if (RELU) {
                v.x = fmaxf(v.x, 0.f); v.y = fmaxf(v.y, 0.f);
                v.z = fmaxf(v.z, 0.f); v.w = fmaxf(v.w, 0.f);
            }
            *reinterpret_cast<float4*>(&out[(long)node * Fout + n]) = v;
        }
    }
}

// ---------------- pooling (count fused) ----------------
__global__ void pool_kernel(const float* __restrict__ h, const void* __restrict__ batch, long N) {
    long t = (long)blockIdx.x * blockDim.x + threadIdx.x;
    long node = t >> 5;
    int c = (int)(t & 31);
    if (node >= N) return;
    int g = (int)ldidx(batch, node);
    const float4 v = *reinterpret_cast<const float4*>(h + node * 128 + c * 4);
    redAdd4(&g_sums[g * 128 + c * 4], v.x, v.y, v.z, v.w);
    if (c == 0) atomicAdd(&g_cnt[g], 1.0f);
}

// ---------------- final linear ----------------
__global__ void final_kernel(const float* __restrict__ lw, const float* __restrict__ lb,
                             float* __restrict__ out) {
    __shared__ float sp[128];
    int g = blockIdx.x;
    float inv = 1.0f / fmaxf(g_cnt[g], 1.0f);
    for (int i = threadIdx.x; i < 128; i += 32)
        sp[i] = g_sums[g * 128 + i] * inv;
    __syncthreads();
    if (threadIdx.x < 10) {
        float acc = lb[threadIdx.x];
#pragma unroll 8
        for (int f = 0; f < 128; f++)
            acc += sp[f] * lw[f * 10 + threadIdx.x];
        out[g * 10 + threadIdx.x] = acc;
    }
}

static inline int cdivl(long a, long b) { return (int)((a + b - 1) / b); }

extern "C" void kernel_launch(void* const* d_in, const int* in_sizes, int n_in,
                              void* d_out, int out_size) {
    const float* x    = (const float*)d_in[0];
    const void*  ei   = d_in[1];
    const float* ea   = (const float*)d_in[2];
    const void*  bat  = d_in[3];
    const float* W1   = (const float*)d_in[4];
    const float* b1   = (const float*)d_in[5];
    const float* W2   = (const float*)d_in[6];
    const float* b2   = (const float*)d_in[7];
    const float* W3   = (const float*)d_in[8];
    const float* b3   = (const float*)d_in[9];
    const float* linW = (const float*)d_in[10];
    const float* linB = (const float*)d_in[11];
    float* out = (float*)d_out;

    const long E = in_sizes[2];   // 1.6M
    const long N = in_sizes[3];   // 100k

    float *pTA, *pTB, *pH1, *pH2, *pH3, *pSums, *pCnt;
    cudaGetSymbolAddress((void**)&pTA, g_TA);
    cudaGetSymbolAddress((void**)&pTB, g_TB);
    cudaGetSymbolAddress((void**)&pH1, g_H1);
    cudaGetSymbolAddress((void**)&pH2, g_H2);
    cudaGetSymbolAddress((void**)&pH3, g_H3);
    cudaGetSymbolAddress((void**)&pSums, g_sums);
    cudaGetSymbolAddress((void**)&pCnt, g_cnt);

    // ---- preamble: launch #0..#3 ----
    init_kernel<<<cdivl(N, 256), 256>>>((const unsigned int*)ei, (int)N);
    deg_hist_kernel<<<cdivl(E, 256), 256>>>(ei, ea, E);
    scan_kernel<<<1, 1024>>>((int)N, (int)E);
    scatter_kernel<<<cdivl(E, 256), 256>>>(ei, ea, E);

    // ---- Layer 1 (128 -> 64): launches #4, #5 (ncu -s 5 lands here) ----
    prop_csr_kernel<128><<<cdivl(N * 32, 256), 256>>>(x, pTA, N);
    prop_csr_kernel<128><<<cdivl(N * 32, 256), 256>>>(pTA, pTB, N);
    combine_gemm_kernel<128, 64, true><<<cdivl(N, 64), 256>>>(x, pTA, pTB, W1, b1, pH1, (int)N);

    // ---- Layer 2 (64 -> 64) ----
    prop_csr_kernel<64><<<cdivl(N * 16, 256), 256>>>(pH1, pTA, N);
    prop_csr_kernel<64><<<cdivl(N * 16, 256), 256>>>(pTA, pTB, N);
    combine_gemm_kernel<64, 64, true><<<cdivl(N, 64), 256>>>(pH1, pTA, pTB, W2, b2, pH2, (int)N);

    // ---- Layer 3 (64 -> 128) ----
    prop_csr_kernel<64><<<cdivl(N * 16, 256), 256>>>(pH2, pTA, N);
    prop_csr_kernel<64><<<cdivl(N * 16, 256), 256>>>(pTA, pTB, N);
    combine_gemm_kernel<64, 128, true><<<cdivl(N, 64), 256>>>(pH2, pTA, pTB, W3, b3, pH3, (int)N);

    // ---- global mean pool + linear head ----
    cudaMemsetAsync(pSums, 0, NG * 128 * sizeof(float));
    cudaMemsetAsync(pCnt, 0, NG * sizeof(float));
    pool_kernel<<<cdivl(N * 32, 256), 256>>>(pH3, bat, N);
    final_kernel<<<NG, 32>>>(linW, linB, out);
}

// round 4
// speedup vs baseline: 3.0047x; 1.0825x over previous
#include <cuda_runtime.h>
#include <cuda_bf16.h>
#include <stdint.h>

#define NN 100000
#define NE 1600000
#define NG 64

typedef unsigned long long ull;

// ---------------- static device scratch (allocation-free rule) ----------------
static __device__ float g_deg[NN];
static __device__ int   g_cnti[NN];
static __device__ int   g_rowptr[NN + 1];
static __device__ int   g_offs[NN];
static __device__ int   g_bsum[128];
static __device__ int   g_csr_src[NE];
static __device__ float g_csr_w[NE];
static __device__ float g_G[(size_t)NN * 192];   // layer-1 fused GEMM out [C|U1|U2]
static __device__ float g_TA[(size_t)NN * 64];
static __device__ float g_TB[(size_t)NN * 64];
static __device__ float g_H1[(size_t)NN * 64];
static __device__ float g_H2[(size_t)NN * 64];
static __device__ float g_H3[(size_t)NN * 128];
static __device__ float g_sums[NG * 128];
static __device__ float g_cnt[NG];
static __device__ int   g_is64;

// ---------------- helpers ----------------
__device__ __forceinline__ long ldidx(const void* p, long i) {
    if (g_is64) return (long)((const long long*)p)[i];
    return (long)((const int*)p)[i];
}

__device__ __forceinline__ float rinv(float d) { return (d > 0.0f) ? rsqrtf(d) : 0.0f; }

__device__ __forceinline__ void redAdd4(float* p, float x, float y, float z, float w) {
    asm volatile("red.global.add.v4.f32 [%0], {%1, %2, %3, %4};"
                 :: "l"(p), "f"(x), "f"(y), "f"(z), "f"(w) : "memory");
}

__device__ __forceinline__ ull pack2(float a, float b) {
    ull r;
    asm("mov.b64 %0, {%1, %2};" : "=l"(r) : "f"(a), "f"(b));
    return r;
}
__device__ __forceinline__ void unpack2(ull v, float& a, float& b) {
    asm("mov.b64 {%0, %1}, %2;" : "=f"(a), "=f"(b) : "l"(v));
}
__device__ __forceinline__ void fma2(ull& d, ull a, ull b) {
    asm("fma.rn.f32x2 %0, %1, %2, %0;" : "+l"(d) : "l"(a), "l"(b));
}

// ---------------- init: zero deg/cnti + index dtype detection ----------------
__global__ void init_kernel(const unsigned int* __restrict__ w, int N) {
    int gid = blockIdx.x * blockDim.x + threadIdx.x;
    if (gid < N) { g_deg[gid] = 0.0f; g_cnti[gid] = 0; }
    if (gid == 0) {
        int is64 = 1;
        for (int i = 0; i < 128; i++) {
            if (w[2 * i + 1] != 0u) { is64 = 0; break; }
        }
        g_is64 = is64;
    }
}

// ---------------- degree (by src) + in-degree histogram (by dst) ----------------
__global__ void deg_hist_kernel(const void* __restrict__ ei, const float* __restrict__ ea, long E) {
    long e = (long)blockIdx.x * blockDim.x + threadIdx.x;
    if (e >= E) return;
    long src = ldidx(ei, e);
    long dst = ldidx(ei, E + e);
    atomicAdd(&g_deg[src], ea[e]);
    atomicAdd(&g_cnti[dst], 1);
}

// ---------------- 2-kernel exclusive scan ----------------
__global__ void scan_local_kernel(int n) {
    __shared__ int sm[1024];
    int gid = blockIdx.x * 1024 + threadIdx.x;
    int v = (gid < n) ? g_cnti[gid] : 0;
    sm[threadIdx.x] = v;
    __syncthreads();
    for (int off = 1; off < 1024; off <<= 1) {
        int t = (threadIdx.x >= off) ? sm[threadIdx.x - off] : 0;
        __syncthreads();
        sm[threadIdx.x] += t;
        __syncthreads();
    }
    if (gid < n) g_rowptr[gid] = sm[threadIdx.x] - v;   // exclusive partial
    if (threadIdx.x == 1023) g_bsum[blockIdx.x] = sm[1023];
}

__global__ void scan_finish_kernel(int n, int E, int nb) {
    __shared__ int pref[128];
    int tid = threadIdx.x;
    if (tid < nb) pref[tid] = g_bsum[tid];
    __syncthreads();
    if (tid == 0) {
        int run = 0;
        for (int i = 0; i < nb; i++) { int v = pref[i]; pref[i] = run; run += v; }
    }
    __syncthreads();
    int gid = blockIdx.x * 1024 + tid;
    if (gid < n) {
        int v = g_rowptr[gid] + pref[blockIdx.x];
        g_rowptr[gid] = v;
        g_offs[gid] = v;
    }
    if (gid == 0) g_rowptr[n] = E;
}

// ---------------- bucket scatter into dst-major CSR, norm folded in ----------------
__global__ void scatter_kernel(const void* __restrict__ ei, const float* __restrict__ ea, long E) {
    long e = (long)blockIdx.x * blockDim.x + threadIdx.x;
    if (e >= E) return;
    int src = (int)ldidx(ei, e);
    int dst = (int)ldidx(ei, E + e);
    int pos = atomicAdd(&g_offs[dst], 1);
    g_csr_src[pos] = src;
    g_csr_w[pos] = -rinv(g_deg[src]) * ea[e] * rinv(g_deg[dst]);
}

// ---------------- layer-1 fused GEMM: G = x @ [W0-W2 | W1 | 2*W2]  (128 -> 192) ----------------
__global__ void gemm_l1_kernel(const float* __restrict__ x, const float* __restrict__ W,
                               float* __restrict__ out, int N) {
    constexpr int BM = 64, BK = 16, BN = 192, Fin = 128;
    constexpr int TN = 12, TNH = 6, SAS = 68;
    constexpr int S = 128 * 64;
    __shared__ float sA[BK * SAS];
    __shared__ float sB[BK * BN];
    const int tid = threadIdx.x;
    const int tx = tid % 16, ty = tid / 16;
    const int base = blockIdx.x * BM;

    ull acc[4][TNH];
#pragma unroll
    for (int i = 0; i < 4; i++)
#pragma unroll
        for (int j = 0; j < TNH; j++) acc[i][j] = 0ull;

    for (int f0 = 0; f0 < Fin; f0 += BK) {
        {
            int kk = tid % 16, mb = tid / 16;
#pragma unroll
            for (int i = 0; i < 4; i++) {
                int m = mb + i * 16;
                int node = base + m;
                sA[kk * SAS + m] = (node < N) ? x[(long)node * Fin + f0 + kk] : 0.f;
            }
        }
        for (int i = tid; i < BK * BN; i += 256) {
            int kk = i / BN, n = i % BN;
            int f = f0 + kk, chunk = n >> 6, nc = n & 63;
            float v;
            if (chunk == 0)      v = W[f * 64 + nc] - W[2 * S + f * 64 + nc];
            else if (chunk == 1) v = W[S + f * 64 + nc];
            else                 v = 2.f * W[2 * S + f * 64 + nc];
            sB[kk * BN + n] = v;
        }
        __syncthreads();
#pragma unroll
        for (int kk = 0; kk < BK; kk++) {
            float4 av = *reinterpret_cast<const float4*>(&sA[kk * SAS + ty * 4]);
            ull ap[4];
            ap[0] = pack2(av.x, av.x); ap[1] = pack2(av.y, av.y);
            ap[2] = pack2(av.z, av.z); ap[3] = pack2(av.w, av.w);
            ull bv[TNH];
#pragma unroll
            for (int j = 0; j < TNH; j++)
                bv[j] = *reinterpret_cast<const ull*>(&sB[kk * BN + tx * TN + 2 * j]);
#pragma unroll
            for (int i = 0; i < 4; i++)
#pragma unroll
                for (int j = 0; j < TNH; j++)
                    fma2(acc[i][j], ap[i], bv[j]);
        }
        __syncthreads();
    }

#pragma unroll
    for (int i = 0; i < 4; i++) {
        int node = base + ty * 4 + i;
        if (node >= N) continue;
#pragma unroll
        for (int j = 0; j < TNH; j += 2) {
            int col = tx * TN + 2 * j;
            float4 v;
            unpack2(acc[i][j], v.x, v.y);
            unpack2(acc[i][j + 1], v.z, v.w);
            *reinterpret_cast<float4*>(&out[(long)node * BN + col]) = v;
        }
    }
}

// ---------------- 3-term combine GEMM + bias + ReLU (f32x2 packed) ----------------
template <int Fin, int Fout>
__global__ void combine3_kernel(const float* __restrict__ T0, const float* __restrict__ T1,
                                const float* __restrict__ T2, const float* __restrict__ W,
                                const float* __restrict__ bias, float* __restrict__ out, int N) {
    constexpr int BM = 64, BK = 16, BN = Fout, K3 = 3 * Fin;
    constexpr int TN = BN / 16, TNH = TN / 2, SAS = 68;
    constexpr int S = Fin * Fout;
    __shared__ float sA[BK * SAS];
    __shared__ float sB[BK * BN];
    const int tid = threadIdx.x;
    const int tx = tid % 16, ty = tid / 16;
    const int base = blockIdx.x * BM;
    const float* Ts[3] = {T0, T1, T2};

    ull acc[4][TNH];
#pragma unroll
    for (int i = 0; i < 4; i++)
#pragma unroll
        for (int j = 0; j < TNH; j++) acc[i][j] = 0ull;

    for (int kc = 0; kc < K3; kc += BK) {
        const int midx = kc / Fin;
        const int f0 = kc % Fin;
        const float* A = Ts[midx];
        {
            int kk = tid % 16, mb = tid / 16;
#pragma unroll
            for (int i = 0; i < 4; i++) {
                int m = mb + i * 16;
                int node = base + m;
                sA[kk * SAS + m] = (node < N) ? A[(long)node * Fin + f0 + kk] : 0.f;
            }
        }
        for (int i = tid; i < BK * BN; i += 256) {
            int kk = i / BN, n = i % BN;
            int f = f0 + kk;
            float v;
            if (midx == 0)      v = W[f * Fout + n] - W[2 * S + f * Fout + n];
            else if (midx == 1) v = W[S + f * Fout + n];
            else                v = 2.f * W[2 * S + f * Fout + n];
            sB[kk * BN + n] = v;
        }
        __syncthreads();
#pragma unroll
        for (int kk = 0; kk < BK; kk++) {
            float4 av = *reinterpret_cast<const float4*>(&sA[kk * SAS + ty * 4]);
            ull ap[4];
            ap[0] = pack2(av.x, av.x); ap[1] = pack2(av.y, av.y);
            ap[2] = pack2(av.z, av.z); ap[3] = pack2(av.w, av.w);
            ull bv[TNH];
#pragma unroll
            for (int j = 0; j < TNH; j++)
                bv[j] = *reinterpret_cast<const ull*>(&sB[kk * BN + tx * TN + 2 * j]);
#pragma unroll
            for (int i = 0; i < 4; i++)
#pragma unroll
                for (int j = 0; j < TNH; j++)
                    fma2(acc[i][j], ap[i], bv[j]);
        }
        __syncthreads();
    }

#pragma unroll
    for (int i = 0; i < 4; i++) {
        int node = base + ty * 4 + i;
        if (node >= N) continue;
#pragma unroll
        for (int j = 0; j < TNH; j += 2) {
            int col = tx * TN + 2 * j;
            float4 v;
            unpack2(acc[i][j], v.x, v.y);
            unpack2(acc[i][j + 1], v.z, v.w);
            v.x = fmaxf(v.x + bias[col + 0], 0.f);
            v.y = fmaxf(v.y + bias[col + 1], 0.f);
            v.z = fmaxf(v.z + bias[col + 2], 0.f);
            v.w = fmaxf(v.w + bias[col + 3], 0.f);
            *reinterpret_cast<float4*>(&out[(long)node * Fout + col]) = v;
        }
    }
}

// ---------------- dst-major pull propagation, F=64, fused epilogues ----------------
template <bool ADD, bool RELUB>
__global__ void prop64_kernel(const float* __restrict__ x, int xs,
                              const float* __restrict__ add, int as,
                              const float* __restrict__ bias,
                              float* __restrict__ out, long N) {
    long t = (long)blockIdx.x * blockDim.x + threadIdx.x;
    long n = t >> 4;            // 16 threads per node
    int c = (int)(t & 15);
    if (n >= N) return;
    int p = g_rowptr[n], end = g_rowptr[n + 1];
    float4 a0 = {0.f, 0.f, 0.f, 0.f}, a1 = {0.f, 0.f, 0.f, 0.f};
    for (; p + 4 <= end; p += 4) {
        int s0 = g_csr_src[p], s1 = g_csr_src[p + 1], s2 = g_csr_src[p + 2], s3 = g_csr_src[p + 3];
        float w0 = g_csr_w[p], w1 = g_csr_w[p + 1], w2 = g_csr_w[p + 2], w3 = g_csr_w[p + 3];
        float4 v0 = __ldg(reinterpret_cast<const float4*>(x + (long)s0 * xs) + c);
        float4 v1 = __ldg(reinterpret_cast<const float4*>(x + (long)s1 * xs) + c);
        float4 v2 = __ldg(reinterpret_cast<const float4*>(x + (long)s2 * xs) + c);
        float4 v3 = __ldg(reinterpret_cast<const float4*>(x + (long)s3 * xs) + c);
        a0.x += w0 * v0.x; a0.y += w0 * v0.y; a0.z += w0 * v0.z; a0.w += w0 * v0.w;
        a1.x += w1 * v1.x; a1.y += w1 * v1.y; a1.z += w1 * v1.z; a1.w += w1 * v1.w;
        a0.x += w2 * v2.x; a0.y += w2 * v2.y; a0.z += w2 * v2.z; a0.w += w2 * v2.w;
        a1.x += w3 * v3.x; a1.y += w3 * v3.y; a1.z += w3 * v3.z; a1.w += w3 * v3.w;
    }
    for (; p < end; p++) {
        int s0 = g_csr_src[p];
        float w0 = g_csr_w[p];
        float4 v0 = __ldg(reinterpret_cast<const float4*>(x + (long)s0 * xs) + c);
        a0.x += w0 * v0.x; a0.y += w0 * v0.y; a0.z += w0 * v0.z; a0.w += w0 * v0.w;
    }
    a0.x += a1.x; a0.y += a1.y; a0.z += a1.z; a0.w += a1.w;
    if (ADD) {
        float4 u = __ldg(reinterpret_cast<const float4*>(add + n * (long)as) + c);
        a0.x += u.x; a0.y += u.y; a0.z += u.z; a0.w += u.w;
    }
    if (RELUB) {
        float4 b = *reinterpret_cast<const float4*>(bias + 4 * c);
        a0.x = fmaxf(a0.x + b.x, 0.f);
        a0.y = fmaxf(a0.y + b.y, 0.f);
        a0.z = fmaxf(a0.z + b.z, 0.f);
        a0.w = fmaxf(a0.w + b.w, 0.f);
    }
    reinterpret_cast<float4*>(out + n * 64)[c] = a0;
}

// ---------------- pooling (count fused) ----------------
__global__ void pool_kernel(const float* __restrict__ h, const void* __restrict__ batch, long N) {
    long t = (long)blockIdx.x * blockDim.x + threadIdx.x;
    long node = t >> 5;
    int c = (int)(t & 31);
    if (node >= N) return;
    int g = (int)ldidx(batch, node);
    const float4 v = *reinterpret_cast<const float4*>(h + node * 128 + c * 4);
    redAdd4(&g_sums[g * 128 + c * 4], v.x, v.y, v.z, v.w);
    if (c == 0) atomicAdd(&g_cnt[g], 1.0f);
}

// ---------------- final linear ----------------
__global__ void final_kernel(const float* __restrict__ lw, const float* __restrict__ lb,
                             float* __restrict__ out) {
    __shared__ float sp[128];
    int g = blockIdx.x;
    float inv = 1.0f / fmaxf(g_cnt[g], 1.0f);
    for (int i = threadIdx.x; i < 128; i += 32)
        sp[i] = g_sums[g * 128 + i] * inv;
    __syncthreads();
    if (threadIdx.x < 10) {
        float acc = lb[threadIdx.x];
#pragma unroll 8
        for (int f = 0; f < 128; f++)
            acc += sp[f] * lw[f * 10 + threadIdx.x];
        out[g * 10 + threadIdx.x] = acc;
    }
}

static inline int cdivl(long a, long b) { return (int)((a + b - 1) / b); }

extern "C" void kernel_launch(void* const* d_in, const int* in_sizes, int n_in,
                              void* d_out, int out_size) {
    const float* x    = (const float*)d_in[0];
    const void*  ei   = d_in[1];
    const float* ea   = (const float*)d_in[2];
    const void*  bat  = d_in[3];
    const float* W1   = (const float*)d_in[4];
    const float* b1   = (const float*)d_in[5];
    const float* W2   = (const float*)d_in[6];
    const float* b2   = (const float*)d_in[7];
    const float* W3   = (const float*)d_in[8];
    const float* b3   = (const float*)d_in[9];
    const float* linW = (const float*)d_in[10];
    const float* linB = (const float*)d_in[11];
    float* out = (float*)d_out;

    const long E = in_sizes[2];   // 1.6M
    const long N = in_sizes[3];   // 100k

    float *pG, *pTA, *pTB, *pH1, *pH2, *pH3, *pSums, *pCnt;
    cudaGetSymbolAddress((void**)&pG, g_G);
    cudaGetSymbolAddress((void**)&pTA, g_TA);
    cudaGetSymbolAddress((void**)&pTB, g_TB);
    cudaGetSymbolAddress((void**)&pH1, g_H1);
    cudaGetSymbolAddress((void**)&pH2, g_H2);
    cudaGetSymbolAddress((void**)&pH3, g_H3);
    cudaGetSymbolAddress((void**)&pSums, g_sums);
    cudaGetSymbolAddress((void**)&pCnt, g_cnt);

    const int nScanBlocks = cdivl(N, 1024);   // 98

    // ---- preamble: launches #0..#4 ----
    init_kernel<<<cdivl(N, 256), 256>>>((const unsigned int*)ei, (int)N);
    deg_hist_kernel<<<cdivl(E, 256), 256>>>(ei, ea, E);
    scan_local_kernel<<<nScanBlocks, 1024>>>((int)N);
    scan_finish_kernel<<<nScanBlocks, 1024>>>((int)N, (int)E, nScanBlocks);
    scatter_kernel<<<cdivl(E, 256), 256>>>(ei, ea, E);

    // ---- Layer 1 (128 -> 64), restructured: G = x@[W0-W2|W1|2W2]; H1 = relu(C + P(U1 + P(U2)) + b) ----
    gemm_l1_kernel<<<cdivl(N, 64), 256>>>(x, W1, pG, (int)N);                       // launch #5
    prop64_kernel<true, false><<<cdivl(N * 16, 256), 256>>>(pG + 128, 192, pG + 64, 192, nullptr, pTA, N);
    prop64_kernel<true, true><<<cdivl(N * 16, 256), 256>>>(pTA, 64, pG, 192, b1, pH1, N);

    // ---- Layer 2 (64 -> 64) ----
    prop64_kernel<false, false><<<cdivl(N * 16, 256), 256>>>(pH1, 64, nullptr, 0, nullptr, pTA, N);
    prop64_kernel<false, false><<<cdivl(N * 16, 256), 256>>>(pTA, 64, nullptr, 0, nullptr, pTB, N);
    combine3_kernel<64, 64><<<cdivl(N, 64), 256>>>(pH1, pTA, pTB, W2, b2, pH2, (int)N);

    // ---- Layer 3 (64 -> 128) ----
    prop64_kernel<false, false><<<cdivl(N * 16, 256), 256>>>(pH2, 64, nullptr, 0, nullptr, pTA, N);
    prop64_kernel<false, false><<<cdivl(N * 16, 256), 256>>>(pTA, 64, nullptr, 0, nullptr, pTB, N);
    combine3_kernel<64, 128><<<cdivl(N, 64), 256>>>(pH2, pTA, pTB, W3, b3, pH3, (int)N);

    // ---- global mean pool + linear head ----
    cudaMemsetAsync(pSums, 0, NG * 128 * sizeof(float));
    cudaMemsetAsync(pCnt, 0, NG * sizeof(float));
    pool_kernel<<<cdivl(N * 32, 256), 256>>>(pH3, bat, N);
    final_kernel<<<NG, 32>>>(linW, linB, out);
}